// round 3
// baseline (speedup 1.0000x reference)
#include <cuda_runtime.h>
#include <cstddef>

// ---------------- problem constants ----------------
#define Tt      4
#define Bt      64
#define BpC     16      // Bt / Tt
#define Cc      512
#define Nn      512
#define Hh      8
#define GD      64      // Cc / Hh
#define TAU     0.5f
#define THRESH  1.0f
#define SCALE   0.125f
#define EPSBN   1e-5f

#define SZ      (Bt*Cc*Nn)      // 16,777,216 elements per [B,C,N] tensor

typedef unsigned long long ull;

// ---------------- scratch (device globals; no allocation) ----------------
__device__ float g_pre[3ll*SZ];   // pre-LIF conv outputs for q,k,v
__device__ float g_spk[3ll*SZ];   // spikes q,k,v (0.0/1.0)
__device__ float g_so [SZ];       // spikes of attention output

// ---------------- packed fp32x2 helpers ----------------
static __device__ __forceinline__ void ffma2(ull& d, ull a, ull b) {
    asm("fma.rn.f32x2 %0, %1, %2, %0;" : "+l"(d) : "l"(a), "l"(b));
}
static __device__ __forceinline__ ull bcast2(float w) {
    ull r; asm("mov.b64 %0, {%1, %1};" : "=l"(r) : "f"(w)); return r;
}
static __device__ __forceinline__ float2 unpack2(ull v) {
    float2 f; asm("mov.b64 {%0, %1}, %2;" : "=f"(f.x), "=f"(f.y) : "l"(v)); return f;
}

// =====================================================================
// conv_bn kernel: out[b] = BN(W @ in[b]) for one batch b.
// 128x128 output tile per block, K-chunk 8, double-buffered smem,
// 8x8 per-thread micro-tile using packed f32x2 FMA.
// mode 0..2: in = ext_in (x), out = g_pre + mode*SZ
// mode 3   : in = g_so,       out = ext_out (d_out)
// =====================================================================
__global__ __launch_bounds__(256) void conv_bn_kernel(
    const float* __restrict__ ext_in, float* __restrict__ ext_out,
    const float* __restrict__ w,
    const float* __restrict__ bng, const float* __restrict__ bnb,
    const float* __restrict__ bnm, const float* __restrict__ bnv,
    int bnrow, int mode)
{
    const float* in;
    float* out;
    if (mode < 3) { in = ext_in; out = g_pre + (size_t)mode * SZ; }
    else          { in = g_so;   out = ext_out; }

    const int b  = blockIdx.z;
    const int r0 = blockIdx.y * 128;
    const int c0 = blockIdx.x * 128;
    const float* inb  = in  + (size_t)b * Cc * Nn;
    float*       outb = out + (size_t)b * Cc * Nn;

    __shared__ __align__(16) float Ws[2][8][132];   // [k][m] transposed W tile
    __shared__ __align__(16) float Xs[2][8][128];   // [k][n] X tile

    const int tid = threadIdx.x;
    const int ty  = tid >> 4;        // 0..15 -> 8 rows each
    const int tx  = tid & 15;        // 0..15 -> 8 cols each

    // load-index assignments
    const int wm  = tid >> 1;              // W row 0..127
    const int wk4 = (tid & 1) * 4;         // W k-quad
    const int xk  = tid >> 5;              // X k-row 0..7
    const int xq  = (tid & 31) * 4;        // X col quad

    ull acc[8][4];
    #pragma unroll
    for (int i = 0; i < 8; i++)
        #pragma unroll
        for (int p = 0; p < 4; p++) acc[i][p] = 0ull;

    // prefetch + store tile 0
    float4 rW = *(const float4*)&w[(size_t)(r0 + wm) * Cc + wk4];
    float4 rX = *(const float4*)&inb[(size_t)xk * Nn + c0 + xq];
    Ws[0][wk4+0][wm] = rW.x; Ws[0][wk4+1][wm] = rW.y;
    Ws[0][wk4+2][wm] = rW.z; Ws[0][wk4+3][wm] = rW.w;
    *(float4*)&Xs[0][xk][xq] = rX;

    const int NIT = Cc / 8;   // 64
    for (int it = 0; it < NIT; it++) {
        __syncthreads();
        const int s = it & 1;
        if (it + 1 < NIT) {
            const int k0 = (it + 1) * 8;
            rW = *(const float4*)&w[(size_t)(r0 + wm) * Cc + k0 + wk4];
            rX = *(const float4*)&inb[(size_t)(k0 + xk) * Nn + c0 + xq];
        }
        #pragma unroll
        for (int kk = 0; kk < 8; kk++) {
            float4 wa = *(const float4*)&Ws[s][kk][ty*8];
            float4 wb = *(const float4*)&Ws[s][kk][ty*8 + 4];
            ulonglong2 xA = *(const ulonglong2*)&Xs[s][kk][tx*8];
            ulonglong2 xB = *(const ulonglong2*)&Xs[s][kk][tx*8 + 4];
            const ull xs0 = xA.x, xs1 = xA.y, xs2 = xB.x, xs3 = xB.y;
            float wr[8] = {wa.x, wa.y, wa.z, wa.w, wb.x, wb.y, wb.z, wb.w};
            #pragma unroll
            for (int i = 0; i < 8; i++) {
                ull wb2 = bcast2(wr[i]);
                ffma2(acc[i][0], wb2, xs0);
                ffma2(acc[i][1], wb2, xs1);
                ffma2(acc[i][2], wb2, xs2);
                ffma2(acc[i][3], wb2, xs3);
            }
        }
        if (it + 1 < NIT) {
            const int ns = s ^ 1;
            Ws[ns][wk4+0][wm] = rW.x; Ws[ns][wk4+1][wm] = rW.y;
            Ws[ns][wk4+2][wm] = rW.z; Ws[ns][wk4+3][wm] = rW.w;
            *(float4*)&Xs[ns][xk][xq] = rX;
        }
    }

    // epilogue: BN affine, store fp32
    #pragma unroll
    for (int i = 0; i < 8; i++) {
        const int r = r0 + ty*8 + i;
        const float inv  = bng[bnrow*Cc + r] / sqrtf(bnv[bnrow*Cc + r] + EPSBN);
        const float bias = bnb[bnrow*Cc + r] - bnm[bnrow*Cc + r] * inv;
        float2 p0 = unpack2(acc[i][0]), p1 = unpack2(acc[i][1]);
        float2 p2 = unpack2(acc[i][2]), p3 = unpack2(acc[i][3]);
        float4 o0, o1;
        o0.x = p0.x*inv + bias; o0.y = p0.y*inv + bias;
        o0.z = p1.x*inv + bias; o0.w = p1.y*inv + bias;
        o1.x = p2.x*inv + bias; o1.y = p2.y*inv + bias;
        o1.z = p3.x*inv + bias; o1.w = p3.y*inv + bias;
        *(float4*)&outb[(size_t)r * Nn + c0 + tx*8]     = o0;
        *(float4*)&outb[(size_t)r * Nn + c0 + tx*8 + 4] = o1;
    }
}

// =====================================================================
// LIF over the T dimension for the q/k/v pre-activations.
// One thread handles one (sel, b', c, 4-wide n quad) across all 4 t.
// =====================================================================
__global__ __launch_bounds__(256) void lif_qkv_kernel()
{
    const int idx = blockIdx.x * 256 + threadIdx.x;  // < 3 * 2^20
    const int q   = idx & 127;
    const int c   = (idx >> 7) & 511;
    const int bp  = (idx >> 16) & 15;
    const int sel = idx >> 20;

    const float* pre = g_pre + (size_t)sel * SZ;
    float*       spk = g_spk + (size_t)sel * SZ;

    float4 mem = {0.f, 0.f, 0.f, 0.f};
    #pragma unroll
    for (int t = 0; t < 4; t++) {
        const size_t off = (((size_t)(t*BpC + bp) * Cc + c) * Nn) + q*4;
        float4 v = *(const float4*)&pre[off];
        float4 s;
        mem.x = mem.x*TAU + v.x; s.x = (mem.x > THRESH) ? 1.f : 0.f; if (mem.x > THRESH) mem.x = 0.f;
        mem.y = mem.y*TAU + v.y; s.y = (mem.y > THRESH) ? 1.f : 0.f; if (mem.y > THRESH) mem.y = 0.f;
        mem.z = mem.z*TAU + v.z; s.z = (mem.z > THRESH) ? 1.f : 0.f; if (mem.z > THRESH) mem.z = 0.f;
        mem.w = mem.w*TAU + v.w; s.w = (mem.w > THRESH) ? 1.f : 0.f; if (mem.w > THRESH) mem.w = 0.f;
        *(float4*)&spk[off] = s;
    }
}

// =====================================================================
// Attention (reassociated linear form) + LIF, fused per (b', h):
//   M_t = K_t V_t^T   (64x64, inner 512)   for t = 0..3  -> smem
//   out_t = SCALE * M_t^T Q_t              (64x512)
//   LIF over t (per n-tile, membrane in registers) -> g_so spikes
// All arithmetic here is exact in fp32 (binary spikes, integer counts).
// =====================================================================
__global__ __launch_bounds__(256) void attn_kernel()
{
    extern __shared__ __align__(16) float sm[];
    float* Ms = sm;                  // [4][64][64]
    float* Sa = sm + 4*64*64;        // staging [64][68]  (K^T, later Q)
    float* Sb = Sa + 64*68;          // staging [64][68]  (V^T)

    const int bp = blockIdx.x;
    const int h  = blockIdx.y;
    const int tid = threadIdx.x;
    const int ty = tid >> 4, tx = tid & 15;
    const int sRow = tid >> 2;           // 0..63  (dk row)
    const int sCol = (tid & 3) * 4;      // base col (0,4,8,12); +16*j covers 0..63

    // ---------- M phase ----------
    for (int t = 0; t < 4; t++) {
        const int b = t*BpC + bp;
        const float* K = g_spk + (size_t)SZ     + ((size_t)b*Cc + h*GD) * Nn;
        const float* V = g_spk + (size_t)2*SZ   + ((size_t)b*Cc + h*GD) * Nn;

        ull accM[4][2];
        #pragma unroll
        for (int i = 0; i < 4; i++) { accM[i][0] = 0ull; accM[i][1] = 0ull; }

        for (int m0 = 0; m0 < Nn; m0 += 64) {
            // each thread loads 4 float4s of K and V: full 64x64 tiles
            float4 kv[4], vv[4];
            #pragma unroll
            for (int j = 0; j < 4; j++) {
                kv[j] = *(const float4*)&K[(size_t)sRow * Nn + m0 + sCol + 16*j];
                vv[j] = *(const float4*)&V[(size_t)sRow * Nn + m0 + sCol + 16*j];
            }
            __syncthreads();
            #pragma unroll
            for (int j = 0; j < 4; j++) {
                const int m = sCol + 16*j;
                Sa[(m+0)*68 + sRow] = kv[j].x; Sa[(m+1)*68 + sRow] = kv[j].y;
                Sa[(m+2)*68 + sRow] = kv[j].z; Sa[(m+3)*68 + sRow] = kv[j].w;
                Sb[(m+0)*68 + sRow] = vv[j].x; Sb[(m+1)*68 + sRow] = vv[j].y;
                Sb[(m+2)*68 + sRow] = vv[j].z; Sb[(m+3)*68 + sRow] = vv[j].w;
            }
            __syncthreads();
            #pragma unroll 8
            for (int mm = 0; mm < 64; mm++) {
                float4 ka = *(const float4*)&Sa[mm*68 + ty*4];
                ulonglong2 vp = *(const ulonglong2*)&Sb[mm*68 + tx*4];
                const float kf[4] = {ka.x, ka.y, ka.z, ka.w};
                #pragma unroll
                for (int i = 0; i < 4; i++) {
                    ull kb = bcast2(kf[i]);
                    ffma2(accM[i][0], kb, vp.x);
                    ffma2(accM[i][1], kb, vp.y);
                }
            }
        }
        #pragma unroll
        for (int i = 0; i < 4; i++) {
            float2 a = unpack2(accM[i][0]);
            float2 c2 = unpack2(accM[i][1]);
            float4 mo; mo.x = a.x; mo.y = a.y; mo.z = c2.x; mo.w = c2.y;
            *(float4*)&Ms[t*4096 + (ty*4 + i)*64 + tx*4] = mo;
        }
    }
    __syncthreads();

    // ---------- out phase (with LIF over t) ----------
    for (int n0 = 0; n0 < Nn; n0 += 64) {
        float mem[4][4];
        #pragma unroll
        for (int i = 0; i < 4; i++)
            #pragma unroll
            for (int j = 0; j < 4; j++) mem[i][j] = 0.f;

        for (int t = 0; t < 4; t++) {
            const int b = t*BpC + bp;
            const float* Q = g_spk + ((size_t)b*Cc + h*GD) * Nn;   // sel 0
            float4 qv[4];
            #pragma unroll
            for (int j = 0; j < 4; j++)
                qv[j] = *(const float4*)&Q[(size_t)sRow * Nn + n0 + sCol + 16*j];
            __syncthreads();
            #pragma unroll
            for (int j = 0; j < 4; j++)
                *(float4*)&Sa[sRow*68 + sCol + 16*j] = qv[j];
            __syncthreads();

            ull acc[4][2];
            #pragma unroll
            for (int i = 0; i < 4; i++) { acc[i][0] = 0ull; acc[i][1] = 0ull; }

            #pragma unroll 8
            for (int dk = 0; dk < 64; dk++) {
                float4 mv = *(const float4*)&Ms[t*4096 + dk*64 + ty*4];
                ulonglong2 qp = *(const ulonglong2*)&Sa[dk*68 + tx*4];
                const float mf[4] = {mv.x, mv.y, mv.z, mv.w};
                #pragma unroll
                for (int i = 0; i < 4; i++) {
                    ull mb = bcast2(mf[i]);
                    ffma2(acc[i][0], mb, qp.x);
                    ffma2(acc[i][1], mb, qp.y);
                }
            }

            float* so = g_so + ((size_t)b*Cc + h*GD) * Nn;
            #pragma unroll
            for (int i = 0; i < 4; i++) {
                float2 a = unpack2(acc[i][0]);
                float2 c2 = unpack2(acc[i][1]);
                float o[4] = {a.x, a.y, c2.x, c2.y};
                float s[4];
                #pragma unroll
                for (int j = 0; j < 4; j++) {
                    mem[i][j] = mem[i][j]*TAU + o[j]*SCALE;
                    s[j] = (mem[i][j] > THRESH) ? 1.f : 0.f;
                    if (mem[i][j] > THRESH) mem[i][j] = 0.f;
                }
                float4 sv; sv.x = s[0]; sv.y = s[1]; sv.z = s[2]; sv.w = s[3];
                *(float4*)&so[(size_t)(ty*4 + i) * Nn + n0 + tx*4] = sv;
            }
        }
    }
}

// =====================================================================
// launch
// =====================================================================
extern "C" void kernel_launch(void* const* d_in, const int* in_sizes, int n_in,
                              void* d_out, int out_size)
{
    const float* x     = (const float*)d_in[0];
    const float* wq    = (const float*)d_in[1];
    const float* wk    = (const float*)d_in[2];
    const float* wv    = (const float*)d_in[3];
    const float* wproj = (const float*)d_in[4];
    const float* bng   = (const float*)d_in[5];
    const float* bnb   = (const float*)d_in[6];
    const float* bnm   = (const float*)d_in[7];
    const float* bnv   = (const float*)d_in[8];
    float* out = (float*)d_out;

    const dim3 cgrid(4, 4, 64);   // 512/128 x 512/128 x B
    conv_bn_kernel<<<cgrid, 256>>>(x, out, wq, bng, bnb, bnm, bnv, 0, 0);
    conv_bn_kernel<<<cgrid, 256>>>(x, out, wk, bng, bnb, bnm, bnv, 1, 1);
    conv_bn_kernel<<<cgrid, 256>>>(x, out, wv, bng, bnb, bnm, bnv, 2, 2);

    lif_qkv_kernel<<<12288, 256>>>();

    const int attn_smem = (4*64*64 + 2*64*68) * (int)sizeof(float);  // 100,352 B
    cudaFuncSetAttribute(attn_kernel,
                         cudaFuncAttributeMaxDynamicSharedMemorySize, attn_smem);
    attn_kernel<<<dim3(BpC, Hh), 256, attn_smem>>>();

    conv_bn_kernel<<<cgrid, 256>>>(x, out, wproj, bng, bnb, bnm, bnv, 3, 3);
}

// round 5
// speedup vs baseline: 1.0502x; 1.0502x over previous
#include <cuda_runtime.h>
#include <cuda_bf16.h>
#include <cstdint>
#include <cstddef>

// ---------------- problem constants ----------------
#define Tt      4
#define Bt      64
#define BpC     16
#define Cc      512
#define Nn      512
#define Hh      8
#define GD      64
#define TAU     0.5f
#define THRESH  1.0f
#define SCALE   0.125f
#define EPSBN   1e-5f
#define SZ      (Bt*Cc*Nn)      // 16,777,216

typedef unsigned long long ull;

// ---------------- scratch (device globals) ----------------
__device__ float g_pre[3ll*SZ];           // pre-LIF conv outputs q,k,v  [b][c][n]
__device__ float g_spk[3ll*SZ];           // spikes q,k,v                [b][c][n]
__device__ float g_so [SZ];               // attention-LIF spikes        [b][c][n]
__device__ __nv_bfloat16 g_xhi[SZ];       // x hi split, transposed      [b][n][c]
__device__ __nv_bfloat16 g_xlo[SZ];       // x lo split, transposed      [b][n][c]
__device__ __nv_bfloat16 g_shi[SZ];       // spike hi (exact), transposed[b][n][c]
__device__ __nv_bfloat16 g_whi[4ll*Cc*Cc];
__device__ __nv_bfloat16 g_wlo[4ll*Cc*Cc];

// ---------------- PTX helpers (base PTX only; target sm_103 has no 'a' feats)
static __device__ __forceinline__ uint32_t smem_u32(const void* p) {
    uint32_t a;
    asm("{ .reg .u64 t; cvta.to.shared.u64 t, %1; cvt.u32.u64 %0, t; }" : "=r"(a) : "l"(p));
    return a;
}
static __device__ __forceinline__ void cpasync16(uint32_t dst, const void* src) {
    asm volatile("cp.async.cg.shared.global [%0], [%1], 16;" :: "r"(dst), "l"(src));
}
#define CP_COMMIT()  asm volatile("cp.async.commit_group;" ::: "memory")
#define CP_WAIT(n)   asm volatile("cp.async.wait_group %0;" :: "n"(n) : "memory")

static __device__ __forceinline__ void ldm_x4(uint32_t* r, uint32_t addr) {
    asm volatile("ldmatrix.sync.aligned.m8n8.x4.shared.b16 {%0,%1,%2,%3}, [%4];"
        : "=r"(r[0]), "=r"(r[1]), "=r"(r[2]), "=r"(r[3]) : "r"(addr));
}
static __device__ __forceinline__ void mma16816(float* c, const uint32_t* a, const uint32_t* b) {
    asm volatile("mma.sync.aligned.m16n8k16.row.col.f32.bf16.bf16.f32 "
        "{%0,%1,%2,%3}, {%4,%5,%6,%7}, {%8,%9}, {%0,%1,%2,%3};"
        : "+f"(c[0]), "+f"(c[1]), "+f"(c[2]), "+f"(c[3])
        : "r"(a[0]), "r"(a[1]), "r"(a[2]), "r"(a[3]), "r"(b[0]), "r"(b[1]));
}

// ---------------- fp32x2 helpers (attn kernel) ----------------
static __device__ __forceinline__ void ffma2(ull& d, ull a, ull b) {
    asm("fma.rn.f32x2 %0, %1, %2, %0;" : "+l"(d) : "l"(a), "l"(b));
}
static __device__ __forceinline__ ull bcast2(float w) {
    ull r; asm("mov.b64 %0, {%1, %1};" : "=l"(r) : "f"(w)); return r;
}
static __device__ __forceinline__ float2 unpack2(ull v) {
    float2 f; asm("mov.b64 {%0, %1}, %2;" : "=f"(f.x), "=f"(f.y) : "l"(v)); return f;
}

// =====================================================================
// weight split: fp32 [o][c] -> bf16 hi/lo (same K-major layout)
// =====================================================================
__global__ __launch_bounds__(256) void wsplit_kernel(
    const float* __restrict__ wq, const float* __restrict__ wk,
    const float* __restrict__ wv, const float* __restrict__ wp)
{
    const int which = blockIdx.y;
    const float* w = (which == 0) ? wq : (which == 1) ? wk : (which == 2) ? wv : wp;
    const int i = blockIdx.x * 256 + threadIdx.x;      // < 262144
    float v = w[i];
    __nv_bfloat16 h = __float2bfloat16(v);
    g_whi[(size_t)which * (Cc*Cc) + i] = h;
    g_wlo[(size_t)which * (Cc*Cc) + i] = __float2bfloat16(v - __bfloat162float(h));
}

// =====================================================================
// transpose + split: fp32 [b][c][n] -> bf16 [b][n][c]
// mode 0: x -> g_xhi/g_xlo.   mode 1: g_so -> g_shi (spikes, hi exact)
// =====================================================================
__global__ __launch_bounds__(256) void split_t_kernel(const float* __restrict__ in, int mode)
{
    __shared__ float t[32][33];
    const int b = blockIdx.z, c0 = blockIdx.y * 32, n0 = blockIdx.x * 32;
    const int tx = threadIdx.x, ty = threadIdx.y;       // 32 x 8
    const float* ib = (mode ? (const float*)g_so : in) + (size_t)b * Cc * Nn;
    #pragma unroll
    for (int j = 0; j < 4; j++)
        t[ty + 8*j][tx] = ib[(size_t)(c0 + ty + 8*j) * Nn + n0 + tx];
    __syncthreads();
    #pragma unroll
    for (int j = 0; j < 4; j++) {
        const int n = ty + 8*j;
        const float v = t[tx][n];
        const __nv_bfloat16 h = __float2bfloat16(v);
        const size_t o = ((size_t)b * Nn + n0 + n) * Cc + c0 + tx;
        if (mode == 0) {
            g_xhi[o] = h;
            g_xlo[o] = __float2bfloat16(v - __bfloat162float(h));
        } else {
            g_shi[o] = h;
        }
    }
}

// =====================================================================
// HMMA conv_bn GEMM: D[128m x 128n] = W @ B^T per batch, K=512, + BN
// bf16 3-term split (2-term for proj), mma.sync.m16n8k16, cp.async pipe
// mode 0: merged qkv (blockIdx.y 0..11 -> wsel,r0), B = x splits, out=g_pre
// mode 1: proj (blockIdx.y 0..3), B = g_shi, out = extout
// =====================================================================
#define ROWB   144                      // padded row bytes (64 bf16 + 16B pad)
#define TILEB  (128*ROWB)               // 18432 B per operand tile
#define STAGEB (4*TILEB)                // Ahi|Alo|Bhi|Blo = 73728 B

static __device__ __forceinline__ void stage_load(
    uint32_t st, const __nv_bfloat16* gA, const __nv_bfloat16* gAl,
    const __nv_bfloat16* gB, const __nv_bfloat16* gBl, int terms,
    uint32_t rowOff, int cb0)
{
    #pragma unroll
    for (int j = 0; j < 4; j++) {
        const int c = cb0 + j;
        const uint32_t off = rowOff + c * 16;
        cpasync16(st + off,           gA  + c*8);
        cpasync16(st + TILEB + off,   gAl + c*8);
        cpasync16(st + 2*TILEB + off, gB  + c*8);
        if (terms == 3) cpasync16(st + 3*TILEB + off, gBl + c*8);
    }
}

__global__ __launch_bounds__(256) void hmma_conv(
    float* __restrict__ extout,
    const float* __restrict__ bng, const float* __restrict__ bnb,
    const float* __restrict__ bnm, const float* __restrict__ bnv,
    int mode)
{
    extern __shared__ char smem[];
    const uint32_t sb = smem_u32(smem);
    const int tid  = threadIdx.x;
    const int wid  = tid >> 5, lane = tid & 31;
    const int n0   = blockIdx.x * 128;
    const int b    = blockIdx.z;

    int wsel, r0, terms;
    float* out;
    const __nv_bfloat16 *bh, *bl;
    if (mode == 0) {
        wsel = blockIdx.y >> 2; r0 = (blockIdx.y & 3) * 128; terms = 3;
        out  = g_pre + (size_t)wsel * SZ;
        bh   = g_xhi + ((size_t)b * Nn + n0) * Cc;
        bl   = g_xlo + ((size_t)b * Nn + n0) * Cc;
    } else {
        wsel = 3; r0 = blockIdx.y * 128; terms = 2;
        out  = extout;
        bh   = g_shi + ((size_t)b * Nn + n0) * Cc;
        bl   = bh;   // unused
    }
    const int bnrow = wsel;
    const __nv_bfloat16* wh = g_whi + (size_t)wsel * (Cc*Cc) + (size_t)r0 * Cc;
    const __nv_bfloat16* wl = g_wlo + (size_t)wsel * (Cc*Cc) + (size_t)r0 * Cc;

    // loader indices: 256 threads cover 128 rows x 8 chunks (4 each)
    const int lrow = tid >> 1;
    const int cb0  = (tid & 1) * 4;
    const uint32_t rowOff = (uint32_t)lrow * ROWB;
    const __nv_bfloat16* gA  = wh + (size_t)lrow * Cc;
    const __nv_bfloat16* gAl = wl + (size_t)lrow * Cc;
    const __nv_bfloat16* gB  = bh + (size_t)lrow * Cc;
    const __nv_bfloat16* gBl = bl + (size_t)lrow * Cc;

    float acc[4][4][4];
    #pragma unroll
    for (int i = 0; i < 4; i++)
        #pragma unroll
        for (int j = 0; j < 4; j++)
            #pragma unroll
            for (int q = 0; q < 4; q++) acc[i][j][q] = 0.f;

    const int wm = wid & 1, wn = wid >> 1;      // warp grid 2(M) x 4(N)
    const int grp = lane >> 3, wi = lane & 7;

    stage_load(sb, gA, gAl, gB, gBl, terms, rowOff, cb0);
    CP_COMMIT();

    for (int kc = 0; kc < 8; kc++) {
        const int s = kc & 1;
        if (kc < 7) {
            const int k1 = (kc + 1) * 64;
            stage_load(sb + (s^1)*STAGEB, gA + k1, gAl + k1, gB + k1, gBl + k1,
                       terms, rowOff, cb0);
            CP_COMMIT();
            CP_WAIT(1);
        } else {
            CP_WAIT(0);
        }
        __syncthreads();

        const uint32_t st = sb + s * STAGEB;
        #pragma unroll
        for (int ks = 0; ks < 4; ks++) {
            uint32_t Ah[4][4], Al[4][4], Bh[4][2], Bl[4][2];
            #pragma unroll
            for (int mi = 0; mi < 4; mi++) {
                const uint32_t ra = st
                    + (uint32_t)(wm*64 + mi*16 + wi + (grp&1)*8) * ROWB
                    + (uint32_t)(ks*32 + (grp>>1)*16);
                ldm_x4(Ah[mi], ra);
                ldm_x4(Al[mi], ra + TILEB);
            }
            #pragma unroll
            for (int bt = 0; bt < 2; bt++) {
                const uint32_t rb = st + 2*TILEB
                    + (uint32_t)(wn*32 + bt*16 + wi + (grp>>1)*8) * ROWB
                    + (uint32_t)(ks*32 + (grp&1)*16);
                uint32_t r[4];
                ldm_x4(r, rb);
                Bh[bt*2][0] = r[0]; Bh[bt*2][1] = r[1];
                Bh[bt*2+1][0] = r[2]; Bh[bt*2+1][1] = r[3];
                if (terms == 3) {
                    ldm_x4(r, rb + TILEB);
                    Bl[bt*2][0] = r[0]; Bl[bt*2][1] = r[1];
                    Bl[bt*2+1][0] = r[2]; Bl[bt*2+1][1] = r[3];
                }
            }
            #pragma unroll
            for (int mi = 0; mi < 4; mi++)
                #pragma unroll
                for (int nt = 0; nt < 4; nt++) {
                    mma16816(acc[mi][nt], Ah[mi], Bh[nt]);
                    mma16816(acc[mi][nt], Al[mi], Bh[nt]);
                    if (terms == 3) mma16816(acc[mi][nt], Ah[mi], Bl[nt]);
                }
        }
        __syncthreads();
    }

    // epilogue: BN affine + fp32 store
    #pragma unroll
    for (int mi = 0; mi < 4; mi++) {
        const int rA = r0 + wm*64 + mi*16 + (lane >> 2);
        const int rB = rA + 8;
        const float invA  = bng[bnrow*Cc + rA] / sqrtf(bnv[bnrow*Cc + rA] + EPSBN);
        const float biasA = bnb[bnrow*Cc + rA] - bnm[bnrow*Cc + rA] * invA;
        const float invB  = bng[bnrow*Cc + rB] / sqrtf(bnv[bnrow*Cc + rB] + EPSBN);
        const float biasB = bnb[bnrow*Cc + rB] - bnm[bnrow*Cc + rB] * invB;
        float* oA = out + ((size_t)b * Cc + rA) * Nn + n0;
        float* oB = out + ((size_t)b * Cc + rB) * Nn + n0;
        #pragma unroll
        for (int nt = 0; nt < 4; nt++) {
            const int nc = wn*32 + nt*8 + (lane & 3)*2;
            float2 v0, v1;
            v0.x = acc[mi][nt][0]*invA + biasA;
            v0.y = acc[mi][nt][1]*invA + biasA;
            v1.x = acc[mi][nt][2]*invB + biasB;
            v1.y = acc[mi][nt][3]*invB + biasB;
            *(float2*)&oA[nc] = v0;
            *(float2*)&oB[nc] = v1;
        }
    }
}

// =====================================================================
// LIF over T for q/k/v pre-activations (unchanged, DRAM-bound ~57us)
// =====================================================================
__global__ __launch_bounds__(256) void lif_qkv_kernel()
{
    const int idx = blockIdx.x * 256 + threadIdx.x;
    const int q   = idx & 127;
    const int c   = (idx >> 7) & 511;
    const int bp  = (idx >> 16) & 15;
    const int sel = idx >> 20;

    const float* pre = g_pre + (size_t)sel * SZ;
    float*       spk = g_spk + (size_t)sel * SZ;

    float4 mem = {0.f, 0.f, 0.f, 0.f};
    #pragma unroll
    for (int t = 0; t < 4; t++) {
        const size_t off = (((size_t)(t*BpC + bp) * Cc + c) * Nn) + q*4;
        float4 v = *(const float4*)&pre[off];
        float4 s;
        mem.x = mem.x*TAU + v.x; s.x = (mem.x > THRESH) ? 1.f : 0.f; if (mem.x > THRESH) mem.x = 0.f;
        mem.y = mem.y*TAU + v.y; s.y = (mem.y > THRESH) ? 1.f : 0.f; if (mem.y > THRESH) mem.y = 0.f;
        mem.z = mem.z*TAU + v.z; s.z = (mem.z > THRESH) ? 1.f : 0.f; if (mem.z > THRESH) mem.z = 0.f;
        mem.w = mem.w*TAU + v.w; s.w = (mem.w > THRESH) ? 1.f : 0.f; if (mem.w > THRESH) mem.w = 0.f;
        *(float4*)&spk[off] = s;
    }
}

// =====================================================================
// Attention (reassociated) + LIF, fused per (b', h)  (proven correct)
// =====================================================================
__global__ __launch_bounds__(256) void attn_kernel()
{
    extern __shared__ __align__(16) float sm[];
    float* Ms = sm;                  // [4][64][64]
    float* Sa = sm + 4*64*64;        // staging [64][68]
    float* Sb = Sa + 64*68;          // staging [64][68]

    const int bp = blockIdx.x;
    const int h  = blockIdx.y;
    const int tid = threadIdx.x;
    const int ty = tid >> 4, tx = tid & 15;
    const int sRow = tid >> 2;
    const int sCol = (tid & 3) * 4;

    for (int t = 0; t < 4; t++) {
        const int b = t*BpC + bp;
        const float* K = g_spk + (size_t)SZ   + ((size_t)b*Cc + h*GD) * Nn;
        const float* V = g_spk + (size_t)2*SZ + ((size_t)b*Cc + h*GD) * Nn;

        ull accM[4][2];
        #pragma unroll
        for (int i = 0; i < 4; i++) { accM[i][0] = 0ull; accM[i][1] = 0ull; }

        for (int m0 = 0; m0 < Nn; m0 += 64) {
            float4 kv[4], vv[4];
            #pragma unroll
            for (int j = 0; j < 4; j++) {
                kv[j] = *(const float4*)&K[(size_t)sRow * Nn + m0 + sCol + 16*j];
                vv[j] = *(const float4*)&V[(size_t)sRow * Nn + m0 + sCol + 16*j];
            }
            __syncthreads();
            #pragma unroll
            for (int j = 0; j < 4; j++) {
                const int m = sCol + 16*j;
                Sa[(m+0)*68 + sRow] = kv[j].x; Sa[(m+1)*68 + sRow] = kv[j].y;
                Sa[(m+2)*68 + sRow] = kv[j].z; Sa[(m+3)*68 + sRow] = kv[j].w;
                Sb[(m+0)*68 + sRow] = vv[j].x; Sb[(m+1)*68 + sRow] = vv[j].y;
                Sb[(m+2)*68 + sRow] = vv[j].z; Sb[(m+3)*68 + sRow] = vv[j].w;
            }
            __syncthreads();
            #pragma unroll 8
            for (int mm = 0; mm < 64; mm++) {
                float4 ka = *(const float4*)&Sa[mm*68 + ty*4];
                ulonglong2 vp = *(const ulonglong2*)&Sb[mm*68 + tx*4];
                const float kf[4] = {ka.x, ka.y, ka.z, ka.w};
                #pragma unroll
                for (int i = 0; i < 4; i++) {
                    ull kb = bcast2(kf[i]);
                    ffma2(accM[i][0], kb, vp.x);
                    ffma2(accM[i][1], kb, vp.y);
                }
            }
        }
        #pragma unroll
        for (int i = 0; i < 4; i++) {
            float2 a = unpack2(accM[i][0]);
            float2 c2 = unpack2(accM[i][1]);
            float4 mo; mo.x = a.x; mo.y = a.y; mo.z = c2.x; mo.w = c2.y;
            *(float4*)&Ms[t*4096 + (ty*4 + i)*64 + tx*4] = mo;
        }
    }
    __syncthreads();

    for (int n0 = 0; n0 < Nn; n0 += 64) {
        float mem[4][4];
        #pragma unroll
        for (int i = 0; i < 4; i++)
            #pragma unroll
            for (int j = 0; j < 4; j++) mem[i][j] = 0.f;

        for (int t = 0; t < 4; t++) {
            const int b = t*BpC + bp;
            const float* Q = g_spk + ((size_t)b*Cc + h*GD) * Nn;
            float4 qv[4];
            #pragma unroll
            for (int j = 0; j < 4; j++)
                qv[j] = *(const float4*)&Q[(size_t)sRow * Nn + n0 + sCol + 16*j];
            __syncthreads();
            #pragma unroll
            for (int j = 0; j < 4; j++)
                *(float4*)&Sa[sRow*68 + sCol + 16*j] = qv[j];
            __syncthreads();

            ull acc[4][2];
            #pragma unroll
            for (int i = 0; i < 4; i++) { acc[i][0] = 0ull; acc[i][1] = 0ull; }

            #pragma unroll 8
            for (int dk = 0; dk < 64; dk++) {
                float4 mv = *(const float4*)&Ms[t*4096 + dk*64 + ty*4];
                ulonglong2 qp = *(const ulonglong2*)&Sa[dk*68 + tx*4];
                const float mf[4] = {mv.x, mv.y, mv.z, mv.w};
                #pragma unroll
                for (int i = 0; i < 4; i++) {
                    ull mb = bcast2(mf[i]);
                    ffma2(acc[i][0], mb, qp.x);
                    ffma2(acc[i][1], mb, qp.y);
                }
            }

            float* so = g_so + ((size_t)b*Cc + h*GD) * Nn;
            #pragma unroll
            for (int i = 0; i < 4; i++) {
                float2 a = unpack2(acc[i][0]);
                float2 c2 = unpack2(acc[i][1]);
                float o[4] = {a.x, a.y, c2.x, c2.y};
                float s[4];
                #pragma unroll
                for (int j = 0; j < 4; j++) {
                    mem[i][j] = mem[i][j]*TAU + o[j]*SCALE;
                    s[j] = (mem[i][j] > THRESH) ? 1.f : 0.f;
                    if (mem[i][j] > THRESH) mem[i][j] = 0.f;
                }
                float4 sv; sv.x = s[0]; sv.y = s[1]; sv.z = s[2]; sv.w = s[3];
                *(float4*)&so[(size_t)(ty*4 + i) * Nn + n0 + tx*4] = sv;
            }
        }
    }
}

// =====================================================================
// launch
// =====================================================================
extern "C" void kernel_launch(void* const* d_in, const int* in_sizes, int n_in,
                              void* d_out, int out_size)
{
    const float* x     = (const float*)d_in[0];
    const float* wq    = (const float*)d_in[1];
    const float* wk    = (const float*)d_in[2];
    const float* wv    = (const float*)d_in[3];
    const float* wproj = (const float*)d_in[4];
    const float* bng   = (const float*)d_in[5];
    const float* bnb   = (const float*)d_in[6];
    const float* bnm   = (const float*)d_in[7];
    const float* bnv   = (const float*)d_in[8];
    float* out = (float*)d_out;

    const int conv_smem = 2 * STAGEB;   // 147,456 B
    cudaFuncSetAttribute(hmma_conv, cudaFuncAttributeMaxDynamicSharedMemorySize, conv_smem);
    const int attn_smem = (4*64*64 + 2*64*68) * (int)sizeof(float);  // 100,352 B
    cudaFuncSetAttribute(attn_kernel, cudaFuncAttributeMaxDynamicSharedMemorySize, attn_smem);

    wsplit_kernel<<<dim3(1024, 4), 256>>>(wq, wk, wv, wproj);
    split_t_kernel<<<dim3(16, 16, 64), dim3(32, 8)>>>(x, 0);

    // merged q,k,v conv_bn (M = 1536 stacked)
    hmma_conv<<<dim3(4, 12, 64), 256, conv_smem>>>(out, bng, bnb, bnm, bnv, 0);

    lif_qkv_kernel<<<12288, 256>>>();

    attn_kernel<<<dim3(BpC, Hh), 256, attn_smem>>>();

    split_t_kernel<<<dim3(16, 16, 64), dim3(32, 8)>>>(x, 1);   // g_so -> g_shi

    // proj conv_bn
    hmma_conv<<<dim3(4, 4, 64), 256, conv_smem>>>(out, bng, bnb, bnm, bnv, 1);
}

// round 6
// speedup vs baseline: 1.1044x; 1.0515x over previous
#include <cuda_runtime.h>
#include <cuda_bf16.h>
#include <cstdint>
#include <cstddef>

// ---------------- problem constants ----------------
#define Tt      4
#define Bt      64
#define BpC     16
#define Cc      512
#define Nn      512
#define Hh      8
#define GD      64
#define TAU     0.5f
#define THRESH  1.0f
#define SCALE   0.125f
#define EPSBN   1e-5f
#define SZ      (Bt*Cc*Nn)      // 16,777,216

typedef unsigned long long ull;

// ---------------- scratch (device globals) ----------------
__device__ __align__(128) float g_pre[3ll*SZ];     // pre-LIF conv outputs q,k,v [b][c][n]
__device__ __align__(128) float g_spk[3ll*SZ];     // spikes q,k,v               [b][c][n]
__device__ __align__(128) float g_so [SZ];         // attention-LIF spikes       [b][c][n]
__device__ __align__(128) __nv_bfloat16 g_xhi[SZ]; // x hi split, transposed     [b][n][c]
__device__ __align__(128) __nv_bfloat16 g_xlo[SZ]; // x lo split, transposed     [b][n][c]
__device__ __align__(128) __nv_bfloat16 g_shi[SZ]; // spike hi (exact), transp.  [b][n][c]
__device__ __align__(128) __nv_bfloat16 g_whi[4ll*Cc*Cc];
__device__ __align__(128) __nv_bfloat16 g_wlo[4ll*Cc*Cc];

// ---------------- PTX helpers (base PTX only; target sm_103 lacks 'a' feats)
static __device__ __forceinline__ uint32_t smem_u32(const void* p) {
    uint32_t a;
    asm("{ .reg .u64 t; cvta.to.shared.u64 t, %1; cvt.u32.u64 %0, t; }" : "=r"(a) : "l"(p));
    return a;
}
static __device__ __forceinline__ void cpasync16(uint32_t dst, const void* src) {
    asm volatile("cp.async.cg.shared.global [%0], [%1], 16;" :: "r"(dst), "l"(src));
}
#define CP_COMMIT()  asm volatile("cp.async.commit_group;" ::: "memory")
#define CP_WAIT(n)   asm volatile("cp.async.wait_group %0;" :: "n"(n) : "memory")

static __device__ __forceinline__ void ldm_x4(uint32_t* r, uint32_t addr) {
    asm volatile("ldmatrix.sync.aligned.m8n8.x4.shared.b16 {%0,%1,%2,%3}, [%4];"
        : "=r"(r[0]), "=r"(r[1]), "=r"(r[2]), "=r"(r[3]) : "r"(addr));
}
static __device__ __forceinline__ void mma16816(float* c, const uint32_t* a, const uint32_t* b) {
    asm volatile("mma.sync.aligned.m16n8k16.row.col.f32.bf16.bf16.f32 "
        "{%0,%1,%2,%3}, {%4,%5,%6,%7}, {%8,%9}, {%0,%1,%2,%3};"
        : "+f"(c[0]), "+f"(c[1]), "+f"(c[2]), "+f"(c[3])
        : "r"(a[0]), "r"(a[1]), "r"(a[2]), "r"(a[3]), "r"(b[0]), "r"(b[1]));
}

// ---------------- fp32x2 helpers ----------------
static __device__ __forceinline__ void ffma2(ull& d, ull a, ull b) {
    asm("fma.rn.f32x2 %0, %1, %2, %0;" : "+l"(d) : "l"(a), "l"(b));
}
static __device__ __forceinline__ ull bcast2(float w) {
    ull r; asm("mov.b64 %0, {%1, %1};" : "=l"(r) : "f"(w)); return r;
}
static __device__ __forceinline__ float2 unpack2(ull v) {
    float2 f; asm("mov.b64 {%0, %1}, %2;" : "=f"(f.x), "=f"(f.y) : "l"(v)); return f;
}

// =====================================================================
// weight split: fp32 [o][c] -> bf16 hi/lo
// =====================================================================
__global__ __launch_bounds__(256) void wsplit_kernel(
    const float* __restrict__ wq, const float* __restrict__ wk,
    const float* __restrict__ wv, const float* __restrict__ wp)
{
    const int which = blockIdx.y;
    const float* w = (which == 0) ? wq : (which == 1) ? wk : (which == 2) ? wv : wp;
    const int i = blockIdx.x * 256 + threadIdx.x;
    float v = w[i];
    __nv_bfloat16 h = __float2bfloat16(v);
    g_whi[(size_t)which * (Cc*Cc) + i] = h;
    g_wlo[(size_t)which * (Cc*Cc) + i] = __float2bfloat16(v - __bfloat162float(h));
}

// =====================================================================
// transpose + split: fp32 [b][c][n] -> bf16 [b][n][c]
// =====================================================================
__global__ __launch_bounds__(256) void split_t_kernel(const float* __restrict__ in, int mode)
{
    __shared__ float t[32][33];
    const int b = blockIdx.z, c0 = blockIdx.y * 32, n0 = blockIdx.x * 32;
    const int tx = threadIdx.x, ty = threadIdx.y;
    const float* ib = (mode ? (const float*)g_so : in) + (size_t)b * Cc * Nn;
    #pragma unroll
    for (int j = 0; j < 4; j++)
        t[ty + 8*j][tx] = ib[(size_t)(c0 + ty + 8*j) * Nn + n0 + tx];
    __syncthreads();
    #pragma unroll
    for (int j = 0; j < 4; j++) {
        const int n = ty + 8*j;
        const float v = t[tx][n];
        const __nv_bfloat16 h = __float2bfloat16(v);
        const size_t o = ((size_t)b * Nn + n0 + n) * Cc + c0 + tx;
        if (mode == 0) {
            g_xhi[o] = h;
            g_xlo[o] = __float2bfloat16(v - __bfloat162float(h));
        } else {
            g_shi[o] = h;
        }
    }
}

// =====================================================================
// DUAL-PIPE conv_bn: per-batch D[128m x 64n] tiles, K=512, + BN.
// blockIdx.x < hsplit  -> HMMA CTA (bf16 split, tensor pipe)
// blockIdx.x >= hsplit -> FFMA CTA (exact fp32, fma pipe)
// 148 % 8 == 4 => co-resident CTA pairs on an SM get opposite types.
// =====================================================================
#define AROWB   80                       // 32 bf16 = 64B + 16B pad
#define ST_AHI  0
#define ST_ALO  10240
#define ST_BHI  20480
#define ST_BLO  25600
#define STAGE   30720
#define CONV_SMEM (2*STAGE)              // 61440

__global__ __launch_bounds__(256, 2) void conv_dual(
    float* __restrict__ extout, const float* __restrict__ x,
    const float* __restrict__ wq, const float* __restrict__ wk,
    const float* __restrict__ wv, const float* __restrict__ wp,
    const float* __restrict__ bng, const float* __restrict__ bnb,
    const float* __restrict__ bnm, const float* __restrict__ bnv,
    int mode)
{
    extern __shared__ char smem[];
    const int tid = threadIdx.x;
    const int xb  = blockIdx.x;
    const int b   = blockIdx.z;

    int wsel, r0;
    if (mode == 0) { wsel = blockIdx.y >> 2; r0 = (blockIdx.y & 3) * 128; }
    else           { wsel = 3;               r0 = blockIdx.y * 128; }
    const int terms  = (mode == 0) ? 3 : 2;
    const int hsplit = (mode == 0) ? 4 : 5;
    const int n0 = xb * 64;
    float* out = (mode == 0) ? (g_pre + (size_t)wsel * SZ) : extout;
    const int bnrow = wsel;

    if (xb < hsplit) {
        // ---------------- HMMA path (tensor pipe) ----------------
        const uint32_t sb = smem_u32(smem);
        const int wid = tid >> 5, lane = tid & 31;
        const int wm = wid & 1, wn = wid >> 1;
        const int grp = lane >> 3, wi = lane & 7;

        const __nv_bfloat16* wh = g_whi + (size_t)wsel * (Cc*Cc) + (size_t)r0 * Cc;
        const __nv_bfloat16* wl = g_wlo + (size_t)wsel * (Cc*Cc) + (size_t)r0 * Cc;
        const __nv_bfloat16* bh = ((mode == 0) ? g_xhi : g_shi) + ((size_t)b * Nn + n0) * Cc;
        const __nv_bfloat16* bl = g_xlo + ((size_t)b * Nn + n0) * Cc;

        const int arow = tid >> 1, ac0 = (tid & 1) * 2;
        const int brow = tid >> 2, bc  = tid & 3;

        float acc[4][2][4];
        #pragma unroll
        for (int i = 0; i < 4; i++)
            #pragma unroll
            for (int j = 0; j < 2; j++)
                #pragma unroll
                for (int q = 0; q < 4; q++) acc[i][j][q] = 0.f;

        // stage loader
        auto load_stage = [&](uint32_t st, int k0) {
            const __nv_bfloat16* aH = wh + (size_t)arow * Cc + k0;
            const __nv_bfloat16* aL = wl + (size_t)arow * Cc + k0;
            #pragma unroll
            for (int j = 0; j < 2; j++) {
                const int c = ac0 + j;
                const uint32_t off = (uint32_t)arow * AROWB + c * 16;
                cpasync16(st + ST_AHI + off, aH + c*8);
                cpasync16(st + ST_ALO + off, aL + c*8);
            }
            const uint32_t boff = (uint32_t)brow * AROWB + bc * 16;
            cpasync16(st + ST_BHI + boff, bh + (size_t)brow * Cc + k0 + bc*8);
            if (terms == 3)
                cpasync16(st + ST_BLO + boff, bl + (size_t)brow * Cc + k0 + bc*8);
        };

        load_stage(sb, 0);
        CP_COMMIT();

        for (int kc = 0; kc < 16; kc++) {
            const int s = kc & 1;
            if (kc < 15) {
                load_stage(sb + (s^1)*STAGE, (kc + 1) * 32);
                CP_COMMIT();
                CP_WAIT(1);
            } else {
                CP_WAIT(0);
            }
            __syncthreads();

            const uint32_t st = sb + s * STAGE;
            #pragma unroll
            for (int ks = 0; ks < 2; ks++) {
                uint32_t Ah[4][4], Al[4][4], Bh[2][2], Bl[2][2];
                const uint32_t colA = (uint32_t)(ks*32 + (grp>>1)*16);
                #pragma unroll
                for (int mi = 0; mi < 4; mi++) {
                    const uint32_t ra = st + ST_AHI
                        + (uint32_t)(wm*64 + mi*16 + wi + (grp&1)*8) * AROWB + colA;
                    ldm_x4(Ah[mi], ra);
                    ldm_x4(Al[mi], ra + (ST_ALO - ST_AHI));
                }
                const uint32_t rb = st + ST_BHI
                    + (uint32_t)(wn*16 + wi + (grp>>1)*8) * AROWB
                    + (uint32_t)(ks*32 + (grp&1)*16);
                { uint32_t r[4]; ldm_x4(r, rb);
                  Bh[0][0]=r[0]; Bh[0][1]=r[1]; Bh[1][0]=r[2]; Bh[1][1]=r[3]; }
                if (terms == 3) {
                    uint32_t r[4]; ldm_x4(r, rb + (ST_BLO - ST_BHI));
                    Bl[0][0]=r[0]; Bl[0][1]=r[1]; Bl[1][0]=r[2]; Bl[1][1]=r[3];
                }
                #pragma unroll
                for (int mi = 0; mi < 4; mi++)
                    #pragma unroll
                    for (int nt = 0; nt < 2; nt++) {
                        mma16816(acc[mi][nt], Ah[mi], Bh[nt]);
                        mma16816(acc[mi][nt], Al[mi], Bh[nt]);
                        if (terms == 3) mma16816(acc[mi][nt], Ah[mi], Bl[nt]);
                    }
            }
            __syncthreads();
        }

        // epilogue: BN + store
        #pragma unroll
        for (int mi = 0; mi < 4; mi++) {
            const int rA = r0 + wm*64 + mi*16 + (lane >> 2);
            const int rB = rA + 8;
            const float invA  = bng[bnrow*Cc + rA] / sqrtf(bnv[bnrow*Cc + rA] + EPSBN);
            const float biasA = bnb[bnrow*Cc + rA] - bnm[bnrow*Cc + rA] * invA;
            const float invB  = bng[bnrow*Cc + rB] / sqrtf(bnv[bnrow*Cc + rB] + EPSBN);
            const float biasB = bnb[bnrow*Cc + rB] - bnm[bnrow*Cc + rB] * invB;
            float* oA = out + ((size_t)b * Cc + rA) * Nn;
            float* oB = out + ((size_t)b * Cc + rB) * Nn;
            #pragma unroll
            for (int nt = 0; nt < 2; nt++) {
                const int nc = n0 + wn*16 + nt*8 + (lane & 3)*2;
                float2 v0, v1;
                v0.x = acc[mi][nt][0]*invA + biasA;
                v0.y = acc[mi][nt][1]*invA + biasA;
                v1.x = acc[mi][nt][2]*invB + biasB;
                v1.y = acc[mi][nt][3]*invB + biasB;
                *(float2*)&oA[nc] = v0;
                *(float2*)&oB[nc] = v1;
            }
        }
    } else {
        // ---------------- FFMA path (fma pipe, exact fp32) ----------------
        float* Ws = (float*)smem;                 // [2][8][132]
        float* Xs = Ws + 2*8*132;                 // [2][8][68]
        const float* wf = (wsel == 0) ? wq : (wsel == 1) ? wk : (wsel == 2) ? wv : wp;
        const float* fin = ((mode == 0) ? x : (const float*)g_so) + (size_t)b * Cc * Nn;

        const int ty = tid >> 4;       // 16 groups x 8 rows
        const int tx = tid & 15;       // 16 groups x 4 cols
        const int wm = tid >> 1, wk4 = (tid & 1) * 4;
        const int xk = tid >> 4, xq = (tid & 15) * 4;   // tid<128 loads X

        ull acc[8][2];
        #pragma unroll
        for (int i = 0; i < 8; i++) { acc[i][0] = 0ull; acc[i][1] = 0ull; }

        float4 rW = *(const float4*)&wf[(size_t)(r0 + wm) * Cc + wk4];
        float4 rX;
        if (tid < 128) rX = *(const float4*)&fin[(size_t)xk * Nn + n0 + xq];
        Ws[(wk4+0)*132 + wm] = rW.x; Ws[(wk4+1)*132 + wm] = rW.y;
        Ws[(wk4+2)*132 + wm] = rW.z; Ws[(wk4+3)*132 + wm] = rW.w;
        if (tid < 128) *(float4*)&Xs[xk*68 + xq] = rX;

        for (int it = 0; it < 64; it++) {
            __syncthreads();
            const int s = it & 1;
            if (it + 1 < 64) {
                const int k0 = (it + 1) * 8;
                rW = *(const float4*)&wf[(size_t)(r0 + wm) * Cc + k0 + wk4];
                if (tid < 128) rX = *(const float4*)&fin[(size_t)(k0 + xk) * Nn + n0 + xq];
            }
            float* Wss = Ws + s*8*132;
            float* Xss = Xs + s*8*68;
            #pragma unroll
            for (int kk = 0; kk < 8; kk++) {
                float4 wa = *(const float4*)&Wss[kk*132 + ty*8];
                float4 wb = *(const float4*)&Wss[kk*132 + ty*8 + 4];
                ulonglong2 xA = *(const ulonglong2*)&Xss[kk*68 + tx*4];
                float wr[8] = {wa.x, wa.y, wa.z, wa.w, wb.x, wb.y, wb.z, wb.w};
                #pragma unroll
                for (int i = 0; i < 8; i++) {
                    ull wb2 = bcast2(wr[i]);
                    ffma2(acc[i][0], wb2, xA.x);
                    ffma2(acc[i][1], wb2, xA.y);
                }
            }
            if (it + 1 < 64) {
                float* Wsd = Ws + (s^1)*8*132;
                float* Xsd = Xs + (s^1)*8*68;
                Wsd[(wk4+0)*132 + wm] = rW.x; Wsd[(wk4+1)*132 + wm] = rW.y;
                Wsd[(wk4+2)*132 + wm] = rW.z; Wsd[(wk4+3)*132 + wm] = rW.w;
                if (tid < 128) *(float4*)&Xsd[xk*68 + xq] = rX;
            }
        }

        #pragma unroll
        for (int i = 0; i < 8; i++) {
            const int r = r0 + ty*8 + i;
            const float inv  = bng[bnrow*Cc + r] / sqrtf(bnv[bnrow*Cc + r] + EPSBN);
            const float bias = bnb[bnrow*Cc + r] - bnm[bnrow*Cc + r] * inv;
            float2 p0 = unpack2(acc[i][0]), p1 = unpack2(acc[i][1]);
            float4 o;
            o.x = p0.x*inv + bias; o.y = p0.y*inv + bias;
            o.z = p1.x*inv + bias; o.w = p1.y*inv + bias;
            *(float4*)&out[((size_t)b * Cc + r) * Nn + n0 + tx*4] = o;
        }
    }
}

// =====================================================================
// LIF over T for q/k/v pre-activations
// =====================================================================
__global__ __launch_bounds__(256) void lif_qkv_kernel()
{
    const int idx = blockIdx.x * 256 + threadIdx.x;
    const int q   = idx & 127;
    const int c   = (idx >> 7) & 511;
    const int bp  = (idx >> 16) & 15;
    const int sel = idx >> 20;

    const float* pre = g_pre + (size_t)sel * SZ;
    float*       spk = g_spk + (size_t)sel * SZ;

    float4 mem = {0.f, 0.f, 0.f, 0.f};
    #pragma unroll
    for (int t = 0; t < 4; t++) {
        const size_t off = (((size_t)(t*BpC + bp) * Cc + c) * Nn) + q*4;
        float4 v = *(const float4*)&pre[off];
        float4 s;
        mem.x = mem.x*TAU + v.x; s.x = (mem.x > THRESH) ? 1.f : 0.f; if (mem.x > THRESH) mem.x = 0.f;
        mem.y = mem.y*TAU + v.y; s.y = (mem.y > THRESH) ? 1.f : 0.f; if (mem.y > THRESH) mem.y = 0.f;
        mem.z = mem.z*TAU + v.z; s.z = (mem.z > THRESH) ? 1.f : 0.f; if (mem.z > THRESH) mem.z = 0.f;
        mem.w = mem.w*TAU + v.w; s.w = (mem.w > THRESH) ? 1.f : 0.f; if (mem.w > THRESH) mem.w = 0.f;
        *(float4*)&spk[off] = s;
    }
}

// =====================================================================
// Attention (reassociated) + LIF, fused per (b', h)  (proven correct)
// =====================================================================
__global__ __launch_bounds__(256) void attn_kernel()
{
    extern __shared__ __align__(16) float sm[];
    float* Ms = sm;                  // [4][64][64]
    float* Sa = sm + 4*64*64;        // staging [64][68]
    float* Sb = Sa + 64*68;          // staging [64][68]

    const int bp = blockIdx.x;
    const int h  = blockIdx.y;
    const int tid = threadIdx.x;
    const int ty = tid >> 4, tx = tid & 15;
    const int sRow = tid >> 2;
    const int sCol = (tid & 3) * 4;

    for (int t = 0; t < 4; t++) {
        const int b = t*BpC + bp;
        const float* K = g_spk + (size_t)SZ   + ((size_t)b*Cc + h*GD) * Nn;
        const float* V = g_spk + (size_t)2*SZ + ((size_t)b*Cc + h*GD) * Nn;

        ull accM[4][2];
        #pragma unroll
        for (int i = 0; i < 4; i++) { accM[i][0] = 0ull; accM[i][1] = 0ull; }

        for (int m0 = 0; m0 < Nn; m0 += 64) {
            float4 kv[4], vv[4];
            #pragma unroll
            for (int j = 0; j < 4; j++) {
                kv[j] = *(const float4*)&K[(size_t)sRow * Nn + m0 + sCol + 16*j];
                vv[j] = *(const float4*)&V[(size_t)sRow * Nn + m0 + sCol + 16*j];
            }
            __syncthreads();
            #pragma unroll
            for (int j = 0; j < 4; j++) {
                const int m = sCol + 16*j;
                Sa[(m+0)*68 + sRow] = kv[j].x; Sa[(m+1)*68 + sRow] = kv[j].y;
                Sa[(m+2)*68 + sRow] = kv[j].z; Sa[(m+3)*68 + sRow] = kv[j].w;
                Sb[(m+0)*68 + sRow] = vv[j].x; Sb[(m+1)*68 + sRow] = vv[j].y;
                Sb[(m+2)*68 + sRow] = vv[j].z; Sb[(m+3)*68 + sRow] = vv[j].w;
            }
            __syncthreads();
            #pragma unroll 8
            for (int mm = 0; mm < 64; mm++) {
                float4 ka = *(const float4*)&Sa[mm*68 + ty*4];
                ulonglong2 vp = *(const ulonglong2*)&Sb[mm*68 + tx*4];
                const float kf[4] = {ka.x, ka.y, ka.z, ka.w};
                #pragma unroll
                for (int i = 0; i < 4; i++) {
                    ull kb = bcast2(kf[i]);
                    ffma2(accM[i][0], kb, vp.x);
                    ffma2(accM[i][1], kb, vp.y);
                }
            }
        }
        #pragma unroll
        for (int i = 0; i < 4; i++) {
            float2 a = unpack2(accM[i][0]);
            float2 c2 = unpack2(accM[i][1]);
            float4 mo; mo.x = a.x; mo.y = a.y; mo.z = c2.x; mo.w = c2.y;
            *(float4*)&Ms[t*4096 + (ty*4 + i)*64 + tx*4] = mo;
        }
    }
    __syncthreads();

    for (int n0 = 0; n0 < Nn; n0 += 64) {
        float mem[4][4];
        #pragma unroll
        for (int i = 0; i < 4; i++)
            #pragma unroll
            for (int j = 0; j < 4; j++) mem[i][j] = 0.f;

        for (int t = 0; t < 4; t++) {
            const int b = t*BpC + bp;
            const float* Q = g_spk + ((size_t)b*Cc + h*GD) * Nn;
            float4 qv[4];
            #pragma unroll
            for (int j = 0; j < 4; j++)
                qv[j] = *(const float4*)&Q[(size_t)sRow * Nn + n0 + sCol + 16*j];
            __syncthreads();
            #pragma unroll
            for (int j = 0; j < 4; j++)
                *(float4*)&Sa[sRow*68 + sCol + 16*j] = qv[j];
            __syncthreads();

            ull acc[4][2];
            #pragma unroll
            for (int i = 0; i < 4; i++) { acc[i][0] = 0ull; acc[i][1] = 0ull; }

            #pragma unroll 8
            for (int dk = 0; dk < 64; dk++) {
                float4 mv = *(const float4*)&Ms[t*4096 + dk*64 + ty*4];
                ulonglong2 qp = *(const ulonglong2*)&Sa[dk*68 + tx*4];
                const float mf[4] = {mv.x, mv.y, mv.z, mv.w};
                #pragma unroll
                for (int i = 0; i < 4; i++) {
                    ull mb = bcast2(mf[i]);
                    ffma2(acc[i][0], mb, qp.x);
                    ffma2(acc[i][1], mb, qp.y);
                }
            }

            float* so = g_so + ((size_t)b*Cc + h*GD) * Nn;
            #pragma unroll
            for (int i = 0; i < 4; i++) {
                float2 a = unpack2(acc[i][0]);
                float2 c2 = unpack2(acc[i][1]);
                float o[4] = {a.x, a.y, c2.x, c2.y};
                float s[4];
                #pragma unroll
                for (int j = 0; j < 4; j++) {
                    mem[i][j] = mem[i][j]*TAU + o[j]*SCALE;
                    s[j] = (mem[i][j] > THRESH) ? 1.f : 0.f;
                    if (mem[i][j] > THRESH) mem[i][j] = 0.f;
                }
                float4 sv; sv.x = s[0]; sv.y = s[1]; sv.z = s[2]; sv.w = s[3];
                *(float4*)&so[(size_t)(ty*4 + i) * Nn + n0 + tx*4] = sv;
            }
        }
    }
}

// =====================================================================
// launch
// =====================================================================
extern "C" void kernel_launch(void* const* d_in, const int* in_sizes, int n_in,
                              void* d_out, int out_size)
{
    const float* x     = (const float*)d_in[0];
    const float* wq    = (const float*)d_in[1];
    const float* wk    = (const float*)d_in[2];
    const float* wv    = (const float*)d_in[3];
    const float* wproj = (const float*)d_in[4];
    const float* bng   = (const float*)d_in[5];
    const float* bnb   = (const float*)d_in[6];
    const float* bnm   = (const float*)d_in[7];
    const float* bnv   = (const float*)d_in[8];
    float* out = (float*)d_out;

    cudaFuncSetAttribute(conv_dual, cudaFuncAttributeMaxDynamicSharedMemorySize, CONV_SMEM);
    const int attn_smem = (4*64*64 + 2*64*68) * (int)sizeof(float);  // 100,352 B
    cudaFuncSetAttribute(attn_kernel, cudaFuncAttributeMaxDynamicSharedMemorySize, attn_smem);

    wsplit_kernel<<<dim3(1024, 4), 256>>>(wq, wk, wv, wproj);
    split_t_kernel<<<dim3(16, 16, 64), dim3(32, 8)>>>(x, 0);

    // merged q,k,v conv_bn, dual-pipe
    conv_dual<<<dim3(8, 12, 64), 256, CONV_SMEM>>>(out, x, wq, wk, wv, wproj,
                                                   bng, bnb, bnm, bnv, 0);

    lif_qkv_kernel<<<12288, 256>>>();

    attn_kernel<<<dim3(BpC, Hh), 256, attn_smem>>>();

    split_t_kernel<<<dim3(16, 16, 64), dim3(32, 8)>>>(x, 1);   // g_so -> g_shi

    // proj conv_bn, dual-pipe (5:3 tensor:fma)
    conv_dual<<<dim3(8, 4, 64), 256, CONV_SMEM>>>(out, x, wq, wk, wv, wproj,
                                                  bng, bnb, bnm, bnv, 1);
}

// round 8
// speedup vs baseline: 1.5985x; 1.4474x over previous
#include <cuda_runtime.h>
#include <cuda_bf16.h>
#include <cstdint>
#include <cstddef>

// ---------------- problem constants ----------------
#define Tt      4
#define Bt      64
#define BpC     16
#define Cc      512
#define Nn      512
#define Hh      8
#define GD      64
#define TAU     0.5f
#define THRESH  1.0f
#define SCALE   0.125f
#define EPSBN   1e-5f
#define SZ      (Bt*Cc*Nn)      // 16,777,216

typedef unsigned long long ull;

// ---------------- scratch (device globals) ----------------
__device__ __align__(128) float g_pre[3ll*SZ];
__device__ __align__(128) float g_spk[3ll*SZ];
__device__ __align__(128) float g_so [SZ];
__device__ __align__(128) __nv_bfloat16 g_xhi[SZ];
__device__ __align__(128) __nv_bfloat16 g_xlo[SZ];
__device__ __align__(128) __nv_bfloat16 g_shi[SZ];
__device__ __align__(128) __nv_bfloat16 g_whi[4ll*Cc*Cc];
__device__ __align__(128) __nv_bfloat16 g_wlo[4ll*Cc*Cc];

// ---------------- PTX helpers ----------------
static __device__ __forceinline__ uint32_t smem_u32(const void* p) {
    uint32_t a;
    asm("{ .reg .u64 t; cvta.to.shared.u64 t, %1; cvt.u32.u64 %0, t; }" : "=r"(a) : "l"(p));
    return a;
}
static __device__ __forceinline__ void cpasync16(uint32_t dst, const void* src) {
    asm volatile("cp.async.cg.shared.global [%0], [%1], 16;" :: "r"(dst), "l"(src));
}
#define CP_COMMIT()  asm volatile("cp.async.commit_group;" ::: "memory")
#define CP_WAIT(n)   asm volatile("cp.async.wait_group %0;" :: "n"(n) : "memory")

static __device__ __forceinline__ void ldm_x4(uint32_t* r, uint32_t addr) {
    asm volatile("ldmatrix.sync.aligned.m8n8.x4.shared.b16 {%0,%1,%2,%3}, [%4];"
        : "=r"(r[0]), "=r"(r[1]), "=r"(r[2]), "=r"(r[3]) : "r"(addr));
}
static __device__ __forceinline__ void mma16816(float* c, const uint32_t* a, const uint32_t* b) {
    asm volatile("mma.sync.aligned.m16n8k16.row.col.f32.bf16.bf16.f32 "
        "{%0,%1,%2,%3}, {%4,%5,%6,%7}, {%8,%9}, {%0,%1,%2,%3};"
        : "+f"(c[0]), "+f"(c[1]), "+f"(c[2]), "+f"(c[3])
        : "r"(a[0]), "r"(a[1]), "r"(a[2]), "r"(a[3]), "r"(b[0]), "r"(b[1]));
}

// ---------------- fp32x2 helpers (attn kernel) ----------------
static __device__ __forceinline__ void ffma2(ull& d, ull a, ull b) {
    asm("fma.rn.f32x2 %0, %1, %2, %0;" : "+l"(d) : "l"(a), "l"(b));
}
static __device__ __forceinline__ ull bcast2(float w) {
    ull r; asm("mov.b64 %0, {%1, %1};" : "=l"(r) : "f"(w)); return r;
}
static __device__ __forceinline__ float2 unpack2(ull v) {
    float2 f; asm("mov.b64 {%0, %1}, %2;" : "=f"(f.x), "=f"(f.y) : "l"(v)); return f;
}

// =====================================================================
// weight split
// =====================================================================
__global__ __launch_bounds__(256) void wsplit_kernel(
    const float* __restrict__ wq, const float* __restrict__ wk,
    const float* __restrict__ wv, const float* __restrict__ wp)
{
    const int which = blockIdx.y;
    const float* w = (which == 0) ? wq : (which == 1) ? wk : (which == 2) ? wv : wp;
    const int i = blockIdx.x * 256 + threadIdx.x;
    float v = w[i];
    __nv_bfloat16 h = __float2bfloat16(v);
    g_whi[(size_t)which * (Cc*Cc) + i] = h;
    g_wlo[(size_t)which * (Cc*Cc) + i] = __float2bfloat16(v - __bfloat162float(h));
}

// =====================================================================
// transpose + split
// =====================================================================
__global__ __launch_bounds__(256) void split_t_kernel(const float* __restrict__ in, int mode)
{
    __shared__ float t[32][33];
    const int b = blockIdx.z, c0 = blockIdx.y * 32, n0 = blockIdx.x * 32;
    const int tx = threadIdx.x, ty = threadIdx.y;
    const float* ib = (mode ? (const float*)g_so : in) + (size_t)b * Cc * Nn;
    #pragma unroll
    for (int j = 0; j < 4; j++)
        t[ty + 8*j][tx] = ib[(size_t)(c0 + ty + 8*j) * Nn + n0 + tx];
    __syncthreads();
    #pragma unroll
    for (int j = 0; j < 4; j++) {
        const int n = ty + 8*j;
        const float v = t[tx][n];
        const __nv_bfloat16 h = __float2bfloat16(v);
        const size_t o = ((size_t)b * Nn + n0 + n) * Cc + c0 + tx;
        if (mode == 0) {
            g_xhi[o] = h;
            g_xlo[o] = __float2bfloat16(v - __bfloat162float(h));
        } else {
            g_shi[o] = h;
        }
    }
}

// =====================================================================
// HMMA conv_bn GEMM: D[128m x 128n] = W @ B^T per batch, K=512, + BN
// R7: mma issue order TERM-MAJOR (16 independent mmas between acc reuses)
// =====================================================================
#define ROWB   144
#define TILEB  (128*ROWB)
#define STAGEB (4*TILEB)

static __device__ __forceinline__ void stage_load(
    uint32_t st, const __nv_bfloat16* gA, const __nv_bfloat16* gAl,
    const __nv_bfloat16* gB, const __nv_bfloat16* gBl, int terms,
    uint32_t rowOff, int cb0)
{
    #pragma unroll
    for (int j = 0; j < 4; j++) {
        const int c = cb0 + j;
        const uint32_t off = rowOff + c * 16;
        cpasync16(st + off,           gA  + c*8);
        cpasync16(st + TILEB + off,   gAl + c*8);
        cpasync16(st + 2*TILEB + off, gB  + c*8);
        if (terms == 3) cpasync16(st + 3*TILEB + off, gBl + c*8);
    }
}

__global__ __launch_bounds__(256) void hmma_conv(
    float* __restrict__ extout,
    const float* __restrict__ bng, const float* __restrict__ bnb,
    const float* __restrict__ bnm, const float* __restrict__ bnv,
    int mode)
{
    extern __shared__ char smem[];
    const uint32_t sb = smem_u32(smem);
    const int tid  = threadIdx.x;
    const int wid  = tid >> 5, lane = tid & 31;
    const int n0   = blockIdx.x * 128;
    const int b    = blockIdx.z;

    int wsel, r0, terms;
    float* out;
    const __nv_bfloat16 *bh, *bl;
    if (mode == 0) {
        wsel = blockIdx.y >> 2; r0 = (blockIdx.y & 3) * 128; terms = 3;
        out  = g_pre + (size_t)wsel * SZ;
        bh   = g_xhi + ((size_t)b * Nn + n0) * Cc;
        bl   = g_xlo + ((size_t)b * Nn + n0) * Cc;
    } else {
        wsel = 3; r0 = blockIdx.y * 128; terms = 2;
        out  = extout;
        bh   = g_shi + ((size_t)b * Nn + n0) * Cc;
        bl   = bh;
    }
    const int bnrow = wsel;
    const __nv_bfloat16* wh = g_whi + (size_t)wsel * (Cc*Cc) + (size_t)r0 * Cc;
    const __nv_bfloat16* wl = g_wlo + (size_t)wsel * (Cc*Cc) + (size_t)r0 * Cc;

    const int lrow = tid >> 1;
    const int cb0  = (tid & 1) * 4;
    const uint32_t rowOff = (uint32_t)lrow * ROWB;
    const __nv_bfloat16* gA  = wh + (size_t)lrow * Cc;
    const __nv_bfloat16* gAl = wl + (size_t)lrow * Cc;
    const __nv_bfloat16* gB  = bh + (size_t)lrow * Cc;
    const __nv_bfloat16* gBl = bl + (size_t)lrow * Cc;

    float acc[4][4][4];
    #pragma unroll
    for (int i = 0; i < 4; i++)
        #pragma unroll
        for (int j = 0; j < 4; j++)
            #pragma unroll
            for (int q = 0; q < 4; q++) acc[i][j][q] = 0.f;

    const int wm = wid & 1, wn = wid >> 1;
    const int grp = lane >> 3, wi = lane & 7;

    stage_load(sb, gA, gAl, gB, gBl, terms, rowOff, cb0);
    CP_COMMIT();

    for (int kc = 0; kc < 8; kc++) {
        const int s = kc & 1;
        if (kc < 7) {
            const int k1 = (kc + 1) * 64;
            stage_load(sb + (s^1)*STAGEB, gA + k1, gAl + k1, gB + k1, gBl + k1,
                       terms, rowOff, cb0);
            CP_COMMIT();
            CP_WAIT(1);
        } else {
            CP_WAIT(0);
        }
        __syncthreads();

        const uint32_t st = sb + s * STAGEB;
        #pragma unroll
        for (int ks = 0; ks < 4; ks++) {
            uint32_t Ah[4][4], Al[4][4], Bh[4][2], Bl[4][2];
            #pragma unroll
            for (int mi = 0; mi < 4; mi++) {
                const uint32_t ra = st
                    + (uint32_t)(wm*64 + mi*16 + wi + (grp&1)*8) * ROWB
                    + (uint32_t)(ks*32 + (grp>>1)*16);
                ldm_x4(Ah[mi], ra);
                ldm_x4(Al[mi], ra + TILEB);
            }
            #pragma unroll
            for (int bt = 0; bt < 2; bt++) {
                const uint32_t rb = st + 2*TILEB
                    + (uint32_t)(wn*32 + bt*16 + wi + (grp>>1)*8) * ROWB
                    + (uint32_t)(ks*32 + (grp&1)*16);
                uint32_t r[4];
                ldm_x4(r, rb);
                Bh[bt*2][0] = r[0]; Bh[bt*2][1] = r[1];
                Bh[bt*2+1][0] = r[2]; Bh[bt*2+1][1] = r[3];
                if (terms == 3) {
                    ldm_x4(r, rb + TILEB);
                    Bl[bt*2][0] = r[0]; Bl[bt*2][1] = r[1];
                    Bl[bt*2+1][0] = r[2]; Bl[bt*2+1][1] = r[3];
                }
            }
            // ---- TERM-MAJOR issue: 16 independent mmas per pass ----
            #pragma unroll
            for (int mi = 0; mi < 4; mi++)
                #pragma unroll
                for (int nt = 0; nt < 4; nt++)
                    mma16816(acc[mi][nt], Ah[mi], Bh[nt]);
            #pragma unroll
            for (int mi = 0; mi < 4; mi++)
                #pragma unroll
                for (int nt = 0; nt < 4; nt++)
                    mma16816(acc[mi][nt], Al[mi], Bh[nt]);
            if (terms == 3) {
                #pragma unroll
                for (int mi = 0; mi < 4; mi++)
                    #pragma unroll
                    for (int nt = 0; nt < 4; nt++)
                        mma16816(acc[mi][nt], Ah[mi], Bl[nt]);
            }
        }
        __syncthreads();
    }

    // epilogue: BN affine + fp32 store
    #pragma unroll
    for (int mi = 0; mi < 4; mi++) {
        const int rA = r0 + wm*64 + mi*16 + (lane >> 2);
        const int rB = rA + 8;
        const float invA  = bng[bnrow*Cc + rA] / sqrtf(bnv[bnrow*Cc + rA] + EPSBN);
        const float biasA = bnb[bnrow*Cc + rA] - bnm[bnrow*Cc + rA] * invA;
        const float invB  = bng[bnrow*Cc + rB] / sqrtf(bnv[bnrow*Cc + rB] + EPSBN);
        const float biasB = bnb[bnrow*Cc + rB] - bnm[bnrow*Cc + rB] * invB;
        float* pA = out + ((size_t)b * Cc + rA) * Nn + n0;
        float* pB = out + ((size_t)b * Cc + rB) * Nn + n0;
        #pragma unroll
        for (int nt = 0; nt < 4; nt++) {
            const int nc = wn*32 + nt*8 + (lane & 3)*2;
            float2 v0, v1;
            v0.x = acc[mi][nt][0]*invA + biasA;
            v0.y = acc[mi][nt][1]*invA + biasA;
            v1.x = acc[mi][nt][2]*invB + biasB;
            v1.y = acc[mi][nt][3]*invB + biasB;
            *(float2*)&pA[nc] = v0;
            *(float2*)&pB[nc] = v1;
        }
    }
}

// =====================================================================
// LIF over T for q/k/v pre-activations
// =====================================================================
__global__ __launch_bounds__(256) void lif_qkv_kernel()
{
    const int idx = blockIdx.x * 256 + threadIdx.x;
    const int q   = idx & 127;
    const int c   = (idx >> 7) & 511;
    const int bp  = (idx >> 16) & 15;
    const int sel = idx >> 20;

    const float* pre = g_pre + (size_t)sel * SZ;
    float*       spk = g_spk + (size_t)sel * SZ;

    float4 mem = {0.f, 0.f, 0.f, 0.f};
    #pragma unroll
    for (int t = 0; t < 4; t++) {
        const size_t off = (((size_t)(t*BpC + bp) * Cc + c) * Nn) + q*4;
        float4 v = *(const float4*)&pre[off];
        float4 s;
        mem.x = mem.x*TAU + v.x; s.x = (mem.x > THRESH) ? 1.f : 0.f; if (mem.x > THRESH) mem.x = 0.f;
        mem.y = mem.y*TAU + v.y; s.y = (mem.y > THRESH) ? 1.f : 0.f; if (mem.y > THRESH) mem.y = 0.f;
        mem.z = mem.z*TAU + v.z; s.z = (mem.z > THRESH) ? 1.f : 0.f; if (mem.z > THRESH) mem.z = 0.f;
        mem.w = mem.w*TAU + v.w; s.w = (mem.w > THRESH) ? 1.f : 0.f; if (mem.w > THRESH) mem.w = 0.f;
        *(float4*)&spk[off] = s;
    }
}

// =====================================================================
// Attention (reassociated) + LIF, fused per (b', h)
// =====================================================================
__global__ __launch_bounds__(256) void attn_kernel()
{
    extern __shared__ __align__(16) float sm[];
    float* Ms = sm;
    float* Sa = sm + 4*64*64;
    float* Sb = Sa + 64*68;

    const int bp = blockIdx.x;
    const int h  = blockIdx.y;
    const int tid = threadIdx.x;
    const int ty = tid >> 4, tx = tid & 15;
    const int sRow = tid >> 2;
    const int sCol = (tid & 3) * 4;

    for (int t = 0; t < 4; t++) {
        const int b = t*BpC + bp;
        const float* K = g_spk + (size_t)SZ   + ((size_t)b*Cc + h*GD) * Nn;
        const float* V = g_spk + (size_t)2*SZ + ((size_t)b*Cc + h*GD) * Nn;

        ull accM[4][2];
        #pragma unroll
        for (int i = 0; i < 4; i++) { accM[i][0] = 0ull; accM[i][1] = 0ull; }

        for (int m0 = 0; m0 < Nn; m0 += 64) {
            float4 kv[4], vv[4];
            #pragma unroll
            for (int j = 0; j < 4; j++) {
                kv[j] = *(const float4*)&K[(size_t)sRow * Nn + m0 + sCol + 16*j];
                vv[j] = *(const float4*)&V[(size_t)sRow * Nn + m0 + sCol + 16*j];
            }
            __syncthreads();
            #pragma unroll
            for (int j = 0; j < 4; j++) {
                const int m = sCol + 16*j;
                Sa[(m+0)*68 + sRow] = kv[j].x; Sa[(m+1)*68 + sRow] = kv[j].y;
                Sa[(m+2)*68 + sRow] = kv[j].z; Sa[(m+3)*68 + sRow] = kv[j].w;
                Sb[(m+0)*68 + sRow] = vv[j].x; Sb[(m+1)*68 + sRow] = vv[j].y;
                Sb[(m+2)*68 + sRow] = vv[j].z; Sb[(m+3)*68 + sRow] = vv[j].w;
            }
            __syncthreads();
            #pragma unroll 8
            for (int mm = 0; mm < 64; mm++) {
                float4 ka = *(const float4*)&Sa[mm*68 + ty*4];
                ulonglong2 vp = *(const ulonglong2*)&Sb[mm*68 + tx*4];
                const float kf[4] = {ka.x, ka.y, ka.z, ka.w};
                #pragma unroll
                for (int i = 0; i < 4; i++) {
                    ull kb = bcast2(kf[i]);
                    ffma2(accM[i][0], kb, vp.x);
                    ffma2(accM[i][1], kb, vp.y);
                }
            }
        }
        #pragma unroll
        for (int i = 0; i < 4; i++) {
            float2 a = unpack2(accM[i][0]);
            float2 c2 = unpack2(accM[i][1]);
            float4 mo; mo.x = a.x; mo.y = a.y; mo.z = c2.x; mo.w = c2.y;
            *(float4*)&Ms[t*4096 + (ty*4 + i)*64 + tx*4] = mo;
        }
    }
    __syncthreads();

    for (int n0 = 0; n0 < Nn; n0 += 64) {
        float mem[4][4];
        #pragma unroll
        for (int i = 0; i < 4; i++)
            #pragma unroll
            for (int j = 0; j < 4; j++) mem[i][j] = 0.f;

        for (int t = 0; t < 4; t++) {
            const int b = t*BpC + bp;
            const float* Q = g_spk + ((size_t)b*Cc + h*GD) * Nn;
            float4 qv[4];
            #pragma unroll
            for (int j = 0; j < 4; j++)
                qv[j] = *(const float4*)&Q[(size_t)sRow * Nn + n0 + sCol + 16*j];
            __syncthreads();
            #pragma unroll
            for (int j = 0; j < 4; j++)
                *(float4*)&Sa[sRow*68 + sCol + 16*j] = qv[j];
            __syncthreads();

            ull acc[4][2];
            #pragma unroll
            for (int i = 0; i < 4; i++) { acc[i][0] = 0ull; acc[i][1] = 0ull; }

            #pragma unroll 8
            for (int dk = 0; dk < 64; dk++) {
                float4 mv = *(const float4*)&Ms[t*4096 + dk*64 + ty*4];
                ulonglong2 qp = *(const ulonglong2*)&Sa[dk*68 + tx*4];
                const float mf[4] = {mv.x, mv.y, mv.z, mv.w};
                #pragma unroll
                for (int i = 0; i < 4; i++) {
                    ull mb = bcast2(mf[i]);
                    ffma2(acc[i][0], mb, qp.x);
                    ffma2(acc[i][1], mb, qp.y);
                }
            }

            float* so = g_so + ((size_t)b*Cc + h*GD) * Nn;
            #pragma unroll
            for (int i = 0; i < 4; i++) {
                float2 a = unpack2(acc[i][0]);
                float2 c2 = unpack2(acc[i][1]);
                float o[4] = {a.x, a.y, c2.x, c2.y};
                float s[4];
                #pragma unroll
                for (int j = 0; j < 4; j++) {
                    mem[i][j] = mem[i][j]*TAU + o[j]*SCALE;
                    s[j] = (mem[i][j] > THRESH) ? 1.f : 0.f;
                    if (mem[i][j] > THRESH) mem[i][j] = 0.f;
                }
                float4 sv; sv.x = s[0]; sv.y = s[1]; sv.z = s[2]; sv.w = s[3];
                *(float4*)&so[(size_t)(ty*4 + i) * Nn + n0 + tx*4] = sv;
            }
        }
    }
}

// =====================================================================
// launch
// =====================================================================
extern "C" void kernel_launch(void* const* d_in, const int* in_sizes, int n_in,
                              void* d_out, int out_size)
{
    const float* x     = (const float*)d_in[0];
    const float* wq    = (const float*)d_in[1];
    const float* wk    = (const float*)d_in[2];
    const float* wv    = (const float*)d_in[3];
    const float* wproj = (const float*)d_in[4];
    const float* bng   = (const float*)d_in[5];
    const float* bnb   = (const float*)d_in[6];
    const float* bnm   = (const float*)d_in[7];
    const float* bnv   = (const float*)d_in[8];
    float* out = (float*)d_out;

    const int conv_smem = 2 * STAGEB;   // 147,456 B
    cudaFuncSetAttribute(hmma_conv, cudaFuncAttributeMaxDynamicSharedMemorySize, conv_smem);
    const int attn_smem = (4*64*64 + 2*64*68) * (int)sizeof(float);  // 100,352 B
    cudaFuncSetAttribute(attn_kernel, cudaFuncAttributeMaxDynamicSharedMemorySize, attn_smem);

    wsplit_kernel<<<dim3(1024, 4), 256>>>(wq, wk, wv, wproj);
    split_t_kernel<<<dim3(16, 16, 64), dim3(32, 8)>>>(x, 0);

    // merged q,k,v conv_bn (M = 1536 stacked)
    hmma_conv<<<dim3(4, 12, 64), 256, conv_smem>>>(out, bng, bnb, bnm, bnv, 0);

    lif_qkv_kernel<<<12288, 256>>>();

    attn_kernel<<<dim3(BpC, Hh), 256, attn_smem>>>();

    split_t_kernel<<<dim3(16, 16, 64), dim3(32, 8)>>>(x, 1);   // g_so -> g_shi

    // proj conv_bn
    hmma_conv<<<dim3(4, 4, 64), 256, conv_smem>>>(out, bng, bnb, bnm, bnv, 1);
}